// round 4
// baseline (speedup 1.0000x reference)
#include <cuda_runtime.h>
#include <cstdint>

#define BSZ 32
#define SEQ_LEN 4096
#define EMBED_DIM 1024
#define PAD_IDX 1
#define SEP_ID 4

#define CHUNKS_PER_ROW 8
#define CHUNK_LEN (SEQ_LEN / CHUNKS_PER_ROW)   // 512

// Scratch for computed positions (allocation-free rule: device global).
__device__ int g_pos[BSZ * SEQ_LEN];

// ---------------------------------------------------------------------------
// Kernel 1: positions, redundant-prefix chunked.
// Block (row, c) computes pos for tokens [c*512, (c+1)*512) of its row.
//   state: fp = min index of PAD over [0..j], ls = max index of SEP over [0..j]
//   pos[j] = (j < fp) ? (j - ls + 2) : 1
// The block first reduces chunks [0..c) (redundant reads, L2-amortized),
// then does an intra-chunk scan with 128 threads x 4 tokens.
// ---------------------------------------------------------------------------
__global__ __launch_bounds__(128, 8)
void positions_kernel(const int* __restrict__ tok32) {
    const int row   = blockIdx.x >> 3;        // 0..31
    const int chunk = blockIdx.x & 7;         // 0..7
    const int t     = threadIdx.x;            // 0..127
    const int lane  = t & 31;
    const int warp  = t >> 5;

    __shared__ int s_fp[4];
    __shared__ int s_ls[4];
    __shared__ int s_is64;
    __shared__ int s_pre_fp, s_pre_ls;

    // ---- dtype probe: int64 tokens have zero high words for values <2^31 ----
    if (t == 0) {
        int odd_nonzero = 0;
        #pragma unroll
        for (int k = 1; k < 64; k += 2) odd_nonzero |= tok32[k];
        s_is64 = (odd_nonzero == 0) ? 1 : 0;
        s_pre_fp = 0x7fffffff;
        s_pre_ls = 0;
    }
    __syncthreads();
    const int is64 = s_is64;

    const long long* tok64 = (const long long*)tok32;

    // ---- reduce preceding chunks [0 .. chunk*CHUNK_LEN) ----
    {
        int fp = 0x7fffffff, ls = 0;
        const int pre_end = chunk * CHUNK_LEN;
        for (int j = t; j < pre_end; j += 128) {
            int v = is64 ? (int)tok64[(size_t)row * SEQ_LEN + j]
                         : tok32[(size_t)row * SEQ_LEN + j];
            if (v == PAD_IDX) fp = min(fp, j);
            if (v == SEP_ID)  ls = max(ls, j);
        }
        #pragma unroll
        for (int d = 16; d > 0; d >>= 1) {
            fp = min(fp, __shfl_xor_sync(0xffffffffu, fp, d));
            ls = max(ls, __shfl_xor_sync(0xffffffffu, ls, d));
        }
        if (lane == 0) {
            atomicMin(&s_pre_fp, fp);
            atomicMax(&s_pre_ls, ls);
        }
    }
    __syncthreads();
    const int pre_fp = s_pre_fp;
    const int pre_ls = s_pre_ls;

    // ---- load my 4 contiguous tokens of this chunk ----
    const int base = chunk * CHUNK_LEN + t * 4; // j of first token
    int tk[4];
    if (is64) {
        const longlong2* p =
            (const longlong2*)(tok64 + (size_t)row * SEQ_LEN + base);
        longlong2 a = p[0];
        longlong2 b = p[1];
        tk[0] = (int)a.x; tk[1] = (int)a.y; tk[2] = (int)b.x; tk[3] = (int)b.y;
    } else {
        const int4* p = (const int4*)(tok32 + (size_t)row * SEQ_LEN + base);
        int4 a = p[0];
        tk[0] = a.x; tk[1] = a.y; tk[2] = a.z; tk[3] = a.w;
    }

    // ---- local aggregate ----
    int fp = 0x7fffffff, ls = 0;
    #pragma unroll
    for (int e = 0; e < 4; e++) {
        int j = base + e;
        if (tk[e] == PAD_IDX) fp = min(fp, j);
        if (tk[e] == SEP_ID)  ls = max(ls, j);
    }

    // ---- inclusive warp scan ----
    int ifp = fp, ils = ls;
    #pragma unroll
    for (int d = 1; d < 32; d <<= 1) {
        int ofp = __shfl_up_sync(0xffffffffu, ifp, d);
        int ols = __shfl_up_sync(0xffffffffu, ils, d);
        if (lane >= d) { ifp = min(ifp, ofp); ils = max(ils, ols); }
    }
    if (lane == 31) { s_fp[warp] = ifp; s_ls[warp] = ils; }
    __syncthreads();

    // ---- combine warp aggregates (only 4 warps) ----
    int exfp = pre_fp, exls = pre_ls;
    #pragma unroll
    for (int wsel = 0; wsel < 3; wsel++) {
        if (warp > wsel) { exfp = min(exfp, s_fp[wsel]); exls = max(exls, s_ls[wsel]); }
    }
    // lane-exclusive within warp:
    int lfp = __shfl_up_sync(0xffffffffu, ifp, 1);
    int lls = __shfl_up_sync(0xffffffffu, ils, 1);
    if (lane > 0) { exfp = min(exfp, lfp); exls = max(exls, lls); }

    // ---- finalize my 4 elements ----
    int* out = g_pos + (size_t)row * SEQ_LEN;
    int fpx = exfp, lsx = exls;
    #pragma unroll
    for (int e = 0; e < 4; e++) {
        int j = base + e;
        if (tk[e] == PAD_IDX) fpx = min(fpx, j);
        if (tk[e] == SEP_ID)  lsx = max(lsx, j);
        out[j] = (j < fpx) ? (j - lsx + 2) : 1;
    }
}

// ---------------------------------------------------------------------------
// Kernel 2: gather v3. 8 rows per block of 256 threads. Thread t copies
// float4 column t of each row: 8 independent LDG.128 (MLP=8) followed by
// 8 STG.128 with evict-first (__stcs) so the 512MB output stream doesn't
// evict the 16.8MB weights table from L2.
// ---------------------------------------------------------------------------
#define ROWS_PER_BLK 8
#define F4_PER_ROW (EMBED_DIM / 4)   // 256

__global__ __launch_bounds__(256, 6)
void gather_kernel(const float4* __restrict__ w, float4* __restrict__ out) {
    const int row0 = blockIdx.x * ROWS_PER_BLK;
    const int t    = threadIdx.x;

    int p[ROWS_PER_BLK];
    #pragma unroll
    for (int r = 0; r < ROWS_PER_BLK; r++) p[r] = g_pos[row0 + r];

    float4 v[ROWS_PER_BLK];
    #pragma unroll
    for (int r = 0; r < ROWS_PER_BLK; r++)
        v[r] = __ldg(w + (size_t)p[r] * F4_PER_ROW + t);

    float4* dst = out + (size_t)row0 * F4_PER_ROW + t;
    #pragma unroll
    for (int r = 0; r < ROWS_PER_BLK; r++)
        __stcs(dst + r * F4_PER_ROW, v[r]);
}

extern "C" void kernel_launch(void* const* d_in, const int* in_sizes, int n_in,
                              void* d_out, int out_size) {
    const int*   tokens  = (const int*)d_in[0];     // int32 or int64 (probed)
    const float* weights = (const float*)d_in[1];   // [4098, 1024] f32
    float* out = (float*)d_out;                     // [32, 4096, 1024] f32

    positions_kernel<<<BSZ * CHUNKS_PER_ROW, 128>>>(tokens);
    gather_kernel<<<(BSZ * SEQ_LEN) / ROWS_PER_BLK, 256>>>(
        (const float4*)weights, (float4*)out);
}

// round 5
// speedup vs baseline: 1.0074x; 1.0074x over previous
#include <cuda_runtime.h>
#include <cstdint>

#define BSZ 32
#define SEQ_LEN 4096
#define EMBED_DIM 1024
#define PAD_IDX 1
#define SEP_ID 4

#define ROWS_PER_BLK 4
#define F4_PER_ROW (EMBED_DIM / 4)       // 256
#define NPOS_BLOCKS BSZ                  // 32 positions blocks
#define NGATHER_BLOCKS ((BSZ * SEQ_LEN) / ROWS_PER_BLK)  // 32768
#define TOK_PER_THREAD (SEQ_LEN / 256)   // 16

// Scratch for computed positions. Zeroed via cudaMemsetAsync before the fused
// kernel; 0 is the "not ready" sentinel (real pos values are in [1, 4097]).
__device__ int g_pos[BSZ * SEQ_LEN];

// ---------------------------------------------------------------------------
// Fused kernel.
//   blocks [0, 32):        positions — per-row scan, 256 thr x 16 tokens.
//   blocks [32, 32+32768): gather — 4 output rows per block, spin on g_pos
//                          sentinel, then MLP=4 copy with evict-first stores.
// ---------------------------------------------------------------------------
__global__ __launch_bounds__(256, 8)
void fused_kernel(const int* __restrict__ tok32,
                  const float4* __restrict__ w,
                  float4* __restrict__ out) {
    const int bid = blockIdx.x;
    const int t   = threadIdx.x;

    if (bid < NPOS_BLOCKS) {
        // ================= positions role =================
        const int row  = bid;
        const int lane = t & 31;
        const int warp = t >> 5;

        __shared__ int s_fp[8];
        __shared__ int s_ls[8];
        __shared__ int s_is64;

        // dtype probe: int64 tokens have zero high words for values < 2^31
        if (t == 0) {
            int odd_nonzero = 0;
            #pragma unroll
            for (int k = 1; k < 64; k += 2) odd_nonzero |= tok32[k];
            s_is64 = (odd_nonzero == 0) ? 1 : 0;
        }
        __syncthreads();
        const int is64 = s_is64;

        // load my 16 contiguous tokens
        const int base = t * TOK_PER_THREAD;
        int tk[TOK_PER_THREAD];
        if (is64) {
            const longlong2* p = (const longlong2*)
                ((const long long*)tok32 + (size_t)row * SEQ_LEN + base);
            #pragma unroll
            for (int q = 0; q < TOK_PER_THREAD / 2; q++) {
                longlong2 a = p[q];
                tk[2 * q]     = (int)a.x;
                tk[2 * q + 1] = (int)a.y;
            }
        } else {
            const int4* p = (const int4*)(tok32 + (size_t)row * SEQ_LEN + base);
            #pragma unroll
            for (int q = 0; q < TOK_PER_THREAD / 4; q++) {
                int4 a = p[q];
                tk[4 * q] = a.x; tk[4 * q + 1] = a.y;
                tk[4 * q + 2] = a.z; tk[4 * q + 3] = a.w;
            }
        }

        // local aggregate: fp = min PAD idx, ls = max SEP idx
        int fp = 0x7fffffff, ls = 0;
        #pragma unroll
        for (int e = 0; e < TOK_PER_THREAD; e++) {
            int j = base + e;
            if (tk[e] == PAD_IDX) fp = min(fp, j);
            if (tk[e] == SEP_ID)  ls = max(ls, j);
        }

        // inclusive warp scan
        int ifp = fp, ils = ls;
        #pragma unroll
        for (int d = 1; d < 32; d <<= 1) {
            int ofp = __shfl_up_sync(0xffffffffu, ifp, d);
            int ols = __shfl_up_sync(0xffffffffu, ils, d);
            if (lane >= d) { ifp = min(ifp, ofp); ils = max(ils, ols); }
        }
        if (lane == 31) { s_fp[warp] = ifp; s_ls[warp] = ils; }
        __syncthreads();

        // exclusive prefix across the 8 warps
        int exfp = 0x7fffffff, exls = 0;
        #pragma unroll
        for (int wsel = 0; wsel < 7; wsel++) {
            if (warp > wsel) { exfp = min(exfp, s_fp[wsel]); exls = max(exls, s_ls[wsel]); }
        }
        // lane-exclusive within warp
        int lfp = __shfl_up_sync(0xffffffffu, ifp, 1);
        int lls = __shfl_up_sync(0xffffffffu, ils, 1);
        if (lane > 0) { exfp = min(exfp, lfp); exls = max(exls, lls); }

        // finalize my 16 elements (values >= 1, releasing the sentinel)
        int* po = g_pos + (size_t)row * SEQ_LEN;
        int fpx = exfp, lsx = exls;
        #pragma unroll
        for (int e = 0; e < TOK_PER_THREAD; e++) {
            int j = base + e;
            if (tk[e] == PAD_IDX) fpx = min(fpx, j);
            if (tk[e] == SEP_ID)  lsx = max(lsx, j);
            po[j] = (j < fpx) ? (j - lsx + 2) : 1;
        }
    } else {
        // ================= gather role =================
        const int row0 = (bid - NPOS_BLOCKS) * ROWS_PER_BLK;

        // spin on the exact words we consume (0 = not ready; pos >= 1)
        const volatile int* vp = g_pos + row0;
        int p0, p1, p2, p3;
        do { p0 = vp[0]; } while (p0 == 0);
        do { p1 = vp[1]; } while (p1 == 0);
        do { p2 = vp[2]; } while (p2 == 0);
        do { p3 = vp[3]; } while (p3 == 0);

        // 4 independent loads in flight (L2 hits after first touch)
        float4 v0 = __ldg(w + (size_t)p0 * F4_PER_ROW + t);
        float4 v1 = __ldg(w + (size_t)p1 * F4_PER_ROW + t);
        float4 v2 = __ldg(w + (size_t)p2 * F4_PER_ROW + t);
        float4 v3 = __ldg(w + (size_t)p3 * F4_PER_ROW + t);

        // evict-first stores: keep the 16.8MB weights table L2-resident
        float4* dst = out + (size_t)row0 * F4_PER_ROW + t;
        __stcs(dst + 0 * F4_PER_ROW, v0);
        __stcs(dst + 1 * F4_PER_ROW, v1);
        __stcs(dst + 2 * F4_PER_ROW, v2);
        __stcs(dst + 3 * F4_PER_ROW, v3);
    }
}

extern "C" void kernel_launch(void* const* d_in, const int* in_sizes, int n_in,
                              void* d_out, int out_size) {
    const int*   tokens  = (const int*)d_in[0];     // int32 or int64 (probed)
    const float* weights = (const float*)d_in[1];   // [4098, 1024] f32
    float* out = (float*)d_out;                     // [32, 4096, 1024] f32

    // Reset the "ready" sentinels (capturable async memset, no allocation).
    void* pos_addr = nullptr;
    cudaGetSymbolAddress(&pos_addr, g_pos);
    cudaMemsetAsync(pos_addr, 0, sizeof(int) * BSZ * SEQ_LEN);

    fused_kernel<<<NPOS_BLOCKS + NGATHER_BLOCKS, 256>>>(
        tokens, (const float4*)weights, (float4*)out);
}